// round 8
// baseline (speedup 1.0000x reference)
#include <cuda_runtime.h>
#include <math.h>

#define MAXN 102400
#define MAXE 1605632
#define NBMAX 64

// ---------------- device scratch (zero-initialized at module load) -----------
__device__ int    g_cnt[MAXN];           // per-row counts (re-zeroed by scan)
__device__ float  g_deg[MAXN];           // weighted degree (re-zeroed by gemm1)
__device__ int    g_rank[MAXE];          // within-row rank of each edge
__device__ int    g_rowptr[MAXN + 1];    // block-local exclusive starts
__device__ int    g_bsums[NBMAX];
__device__ int    g_boffs[NBMAX];        // block offsets (add to rowptr)
__device__ int    g_done;                // decoupled-scan counter (self-reset)
__device__ int    g_rps[MAXN + 1];       // GLOBAL row starts (written by gemm1)
__device__ int2   g_csr[MAXE];           // (col, ew bits)
__device__ float4 g_A4[MAXN * 4];        // xp0 - xp1
__device__ float4 g_B4[MAXN * 4];        // dinv * xp1 (layer-1 gather target)
__device__ float4 g_h4[MAXN * 4];        // h = relu(...)
__device__ float4 g_hs4[MAXN * 4];       // dinv * h   (layer-2 gather target)
__device__ float  g_dinv[MAXN];

// ---------------- helpers -----------------------------------------------------
__device__ __forceinline__ int detect_is64(const int* w) {
    int bad = 0;
    #pragma unroll
    for (int j = 1; j < 128; j += 2) bad |= w[j];
    return bad == 0;
}

__device__ __forceinline__ unsigned long long pack_f2(float lo, float hi) {
    unsigned long long r;
    asm("mov.b64 %0, {%1, %2};" : "=l"(r) : "r"(__float_as_uint(lo)), "r"(__float_as_uint(hi)));
    return r;
}
__device__ __forceinline__ float f2_lo(unsigned long long v) {
    unsigned int lo, hi;
    asm("mov.b64 {%0, %1}, %2;" : "=r"(lo), "=r"(hi) : "l"(v));
    return __uint_as_float(lo);
}
__device__ __forceinline__ float f2_hi(unsigned long long v) {
    unsigned int lo, hi;
    asm("mov.b64 {%0, %1}, %2;" : "=r"(lo), "=r"(hi) : "l"(v));
    return __uint_as_float(hi);
}
#define FFMA2(acc, b, w) asm("fma.rn.f32x2 %0, %1, %2, %0;" : "+l"(acc) : "l"(b), "l"(w))

// ---------------- pass 1: counts + within-row rank (2 edges/thread) ----------
__global__ void k_cnt(const void* __restrict__ ei, int E) {
    __shared__ int s_is64;
    if (threadIdx.x == 0) s_is64 = detect_is64((const int*)ei);
    __syncthreads();
    int e = (blockIdx.x * blockDim.x + threadIdx.x) * 2;
    if (e >= E) return;
    int r0, r1 = -1;
    if (s_is64) {
        longlong2 v = *(const longlong2*)((const long long*)ei + e);
        r0 = (int)v.x;
        if (e + 1 < E) r1 = (int)v.y;
    } else {
        int2 v = *(const int2*)((const int*)ei + e);
        r0 = v.x;
        if (e + 1 < E) r1 = v.y;
    }
    g_rank[e] = atomicAdd(&g_cnt[r0], 1);
    if (r1 >= 0) g_rank[e + 1] = atomicAdd(&g_cnt[r1], 1);
}

// ---------------- scan: per-block local scan + decoupled block-offset scan ---
__global__ void k_scan_local(int N, int E, int NB) {
    __shared__ int warpSums[32];
    __shared__ int s_flag;
    int t = threadIdx.x;
    int base = blockIdx.x * 2048;
    int i0 = base + 2 * t, i1 = i0 + 1;
    int v0 = (i0 < N) ? g_cnt[i0] : 0;
    int v1 = (i1 < N) ? g_cnt[i1] : 0;
    if (i0 < N) g_cnt[i0] = 0;            // reset for next graph replay
    if (i1 < N) g_cnt[i1] = 0;
    int s = v0 + v1;
    int lane = t & 31, wid = t >> 5;
    int incl = s;
    #pragma unroll
    for (int d = 1; d < 32; d <<= 1) {
        int n = __shfl_up_sync(0xffffffffu, incl, d);
        if (lane >= d) incl += n;
    }
    if (lane == 31) warpSums[wid] = incl;
    __syncthreads();
    if (wid == 0) {
        int ws = warpSums[lane];
        int wi = ws;
        #pragma unroll
        for (int d = 1; d < 32; d <<= 1) {
            int n = __shfl_up_sync(0xffffffffu, wi, d);
            if (lane >= d) wi += n;
        }
        warpSums[lane] = wi - ws;
    }
    __syncthreads();
    int excl = warpSums[wid] + incl - s;
    if (i0 < N) g_rowptr[i0] = excl;
    if (i1 < N) g_rowptr[i1] = excl + v0;
    if (t == 1023) g_bsums[blockIdx.x] = warpSums[wid] + incl;

    __syncthreads();
    if (t == 0) {
        __threadfence();
        s_flag = (atomicAdd(&g_done, 1) == NB - 1);
    }
    __syncthreads();
    if (s_flag && t < 32) {
        __threadfence();
        int b0 = (lane < NB) ? g_bsums[lane] : 0;
        int b1 = (lane + 32 < NB) ? g_bsums[lane + 32] : 0;
        int i0s = b0;
        #pragma unroll
        for (int d = 1; d < 32; d <<= 1) {
            int n = __shfl_up_sync(0xffffffffu, i0s, d);
            if (lane >= d) i0s += n;
        }
        int tot0 = __shfl_sync(0xffffffffu, i0s, 31);
        int i1s = b1;
        #pragma unroll
        for (int d = 1; d < 32; d <<= 1) {
            int n = __shfl_up_sync(0xffffffffu, i1s, d);
            if (lane >= d) i1s += n;
        }
        i1s += tot0;
        g_boffs[lane]      = i0s - b0;
        g_boffs[lane + 32] = i1s - b1;
        __syncwarp();
        if (lane == 0) g_done = 0;   // reset for next replay
    }
}

// ---------------- pass 2: scatter into CSR + weighted-degree REDG ------------
__global__ void k_scatter(const void* __restrict__ ei, const float* __restrict__ ew, int E) {
    __shared__ int s_is64;
    __shared__ int s_boffs[NBMAX];
    if (threadIdx.x == 0) s_is64 = detect_is64((const int*)ei);
    if (threadIdx.x < NBMAX) s_boffs[threadIdx.x] = g_boffs[threadIdx.x];
    __syncthreads();
    int e = blockIdx.x * blockDim.x + threadIdx.x;
    if (e < E) {
        int r, c;
        if (s_is64) {
            r = (int)((const long long*)ei)[e];
            c = (int)((const long long*)ei)[(long)E + e];
        } else {
            r = ((const int*)ei)[e];
            c = ((const int*)ei)[E + e];
        }
        float w = ew[e];
        int p = g_rowptr[r] + s_boffs[r >> 11] + g_rank[e];
        g_csr[p] = make_int2(c, __float_as_int(w));
        atomicAdd(&g_deg[r], w);            // REDG, no return
    }
}

// ---------------- GEMM1 (wide-LDS FFMA2) + fused finalize --------------------
// 256 threads = 8 warps x 8 nodes = 64 nodes/block. smem = 48KB.
// W staged k-pair-interleaved (LDS.64); x staged node-pair f32x2 (LDS.128 x2k).
__global__ void __launch_bounds__(256) k_gemm1(const float* __restrict__ x,
                        const float* __restrict__ W0,
                        const float* __restrict__ W1, int N, int E) {
    __shared__ unsigned long long Wsh2[64 * 32];                 // 16 KB
    __shared__ alignas(16) unsigned long long xs2[8][4][128];    // 32 KB
    __shared__ float dvs[8][8];
    __shared__ int s_boffs[NBMAX];
    int t = threadIdx.x;
    if (t < NBMAX) s_boffs[t] = g_boffs[t];
    // Wsh2[k2*32+j] = (W[2k2][j], W[2k2+1][j]), j<16 from W0, j>=16 from W1
    for (int i = t; i < 64 * 32; i += 256) {
        int k2 = i >> 5, j = i & 31;
        float lo, hi;
        if (j < 16) { lo = W0[(2 * k2) * 16 + j];        hi = W0[(2 * k2 + 1) * 16 + j]; }
        else        { lo = W1[(2 * k2) * 16 + (j - 16)]; hi = W1[(2 * k2 + 1) * 16 + (j - 16)]; }
        Wsh2[i] = pack_f2(lo, hi);
    }
    __syncthreads();   // s_boffs ready

    int warp = t >> 5, lane = t & 31;
    int base = (blockIdx.x * 8 + warp) * 8;   // 8 nodes per warp

    // fused finalize: rps + dinv for this warp's 8 nodes
    if (lane < 8) {
        int nd = base + lane;
        float dv = 0.f;
        if (nd < N) {
            g_rps[nd] = g_rowptr[nd] + s_boffs[nd >> 11];
            float d = g_deg[nd];
            dv = (d > 0.f) ? rsqrtf(d) : 0.f;
            g_dinv[nd] = dv;
            g_deg[nd] = 0.f;                 // reset for next replay
        }
        dvs[warp][lane] = dv;
    }
    if (blockIdx.x == 0 && t == 0) g_rps[N] = E;

    // stage x: 4 node-pairs, f32x2 interleaved, k-contiguous (STS.128 pairs)
    #pragma unroll
    for (int p = 0; p < 4; p++) {
        int n0 = base + 2 * p, n1 = n0 + 1;
        float4 v0 = make_float4(0.f, 0.f, 0.f, 0.f), v1 = v0;
        if (n0 < N) v0 = ((const float4*)(x + (size_t)n0 * 128))[lane];
        if (n1 < N) v1 = ((const float4*)(x + (size_t)n1 * 128))[lane];
        ulonglong2* dst = (ulonglong2*)&xs2[warp][p][lane * 4];
        dst[0] = make_ulonglong2(pack_f2(v0.x, v1.x), pack_f2(v0.y, v1.y));
        dst[1] = make_ulonglong2(pack_f2(v0.z, v1.z), pack_f2(v0.w, v1.w));
    }
    __syncthreads();

    unsigned long long a0 = 0ull, a1 = 0ull, a2 = 0ull, a3 = 0ull;
    #pragma unroll 8
    for (int k2 = 0; k2 < 64; k2++) {
        unsigned long long wp = Wsh2[k2 * 32 + lane];     // LDS.64
        float wk0 = f2_lo(wp), wk1 = f2_hi(wp);
        unsigned long long w00 = pack_f2(wk0, wk0);
        unsigned long long w11 = pack_f2(wk1, wk1);
        ulonglong2 b0 = *(const ulonglong2*)&xs2[warp][0][2 * k2];  // LDS.128 bcast
        ulonglong2 b1 = *(const ulonglong2*)&xs2[warp][1][2 * k2];
        ulonglong2 b2 = *(const ulonglong2*)&xs2[warp][2][2 * k2];
        ulonglong2 b3 = *(const ulonglong2*)&xs2[warp][3][2 * k2];
        FFMA2(a0, b0.x, w00); FFMA2(a0, b0.y, w11);
        FFMA2(a1, b1.x, w00); FFMA2(a1, b1.y, w11);
        FFMA2(a2, b2.x, w00); FFMA2(a2, b2.y, w11);
        FFMA2(a3, b3.x, w00); FFMA2(a3, b3.y, w11);
    }

    float* A = (float*)g_A4;
    float* B = (float*)g_B4;
    float accs[8] = { f2_lo(a0), f2_hi(a0), f2_lo(a1), f2_hi(a1),
                      f2_lo(a2), f2_hi(a2), f2_lo(a3), f2_hi(a3) };
    #pragma unroll
    for (int n = 0; n < 8; n++) {
        int nd = base + n;
        float a = accs[n];
        float o = __shfl_xor_sync(0xffffffffu, a, 16);
        if (nd < N) {
            if (lane < 16) A[(size_t)nd * 16 + lane] = a - o;   // xp0 - xp1
            else {
                float dv = dvs[warp][n];
                B[(size_t)nd * 16 + (lane - 16)] = dv * a;      // dinv*xp1
            }
        }
    }
}

// ---------------- layer1: h = relu(A + dinv*agg(B) + b1) ---------------------
__global__ void __launch_bounds__(1024) k_layer1(const float* __restrict__ b1, int N) {
    int t = blockIdx.x * blockDim.x + threadIdx.x;
    int row = t >> 5;
    if (row >= N) return;
    int lane = t & 31, q = lane & 3, slot = lane >> 2;
    int s = g_rps[row];
    int e = g_rps[row + 1];
    float4 acc = make_float4(0.f, 0.f, 0.f, 0.f);
    for (int p = s + slot; p < e; p += 8) {
        int2 ce = g_csr[p];
        float nv = __int_as_float(ce.y);
        float4 v = g_B4[(size_t)ce.x * 4 + q];
        acc.x = fmaf(nv, v.x, acc.x);
        acc.y = fmaf(nv, v.y, acc.y);
        acc.z = fmaf(nv, v.z, acc.z);
        acc.w = fmaf(nv, v.w, acc.w);
    }
    #pragma unroll
    for (int d = 4; d < 32; d <<= 1) {
        acc.x += __shfl_xor_sync(0xffffffffu, acc.x, d);
        acc.y += __shfl_xor_sync(0xffffffffu, acc.y, d);
        acc.z += __shfl_xor_sync(0xffffffffu, acc.z, d);
        acc.w += __shfl_xor_sync(0xffffffffu, acc.w, d);
    }
    if (lane < 4) {
        float dv = g_dinv[row];
        float4 A  = g_A4[(size_t)row * 4 + lane];
        float4 bb = ((const float4*)b1)[lane];
        float4 h;
        h.x = fmaxf(A.x + dv * acc.x + bb.x, 0.f);
        h.y = fmaxf(A.y + dv * acc.y + bb.y, 0.f);
        h.z = fmaxf(A.z + dv * acc.z + bb.z, 0.f);
        h.w = fmaxf(A.w + dv * acc.w + bb.w, 0.f);
        g_h4[(size_t)row * 4 + lane]  = h;
        g_hs4[(size_t)row * 4 + lane] = make_float4(dv * h.x, dv * h.y, dv * h.z, dv * h.w);
    }
}

// ---------------- layer2: agg(hs) + dual GEMV + log_softmax ------------------
__global__ void __launch_bounds__(1024) k_layer2(const float* __restrict__ W20,
                         const float* __restrict__ W21,
                         const float* __restrict__ b2,
                         float* __restrict__ out, int N) {
    __shared__ float Wd[16 * 32];   // W20 - W21
    __shared__ float Wb[16 * 32];   // W21
    int t = threadIdx.x;
    if (t < 512) {
        float w1v = W21[t];
        Wd[t] = W20[t] - w1v;
        Wb[t] = w1v;
    }
    __syncthreads();
    int gt = blockIdx.x * blockDim.x + t;
    int row = gt >> 5;
    if (row >= N) return;
    int lane = t & 31, q = lane & 3, slot = lane >> 2;
    int s = g_rps[row];
    int e = g_rps[row + 1];
    float4 acc = make_float4(0.f, 0.f, 0.f, 0.f);
    for (int p = s + slot; p < e; p += 8) {
        int2 ce = g_csr[p];
        float nv = __int_as_float(ce.y);
        float4 v = g_hs4[(size_t)ce.x * 4 + q];
        acc.x = fmaf(nv, v.x, acc.x);
        acc.y = fmaf(nv, v.y, acc.y);
        acc.z = fmaf(nv, v.z, acc.z);
        acc.w = fmaf(nv, v.w, acc.w);
    }
    #pragma unroll
    for (int d = 4; d < 32; d <<= 1) {
        acc.x += __shfl_xor_sync(0xffffffffu, acc.x, d);
        acc.y += __shfl_xor_sync(0xffffffffu, acc.y, d);
        acc.z += __shfl_xor_sync(0xffffffffu, acc.z, d);
        acc.w += __shfl_xor_sync(0xffffffffu, acc.w, d);
    }
    float4 hv = make_float4(0.f, 0.f, 0.f, 0.f);
    if (lane < 4) hv = g_h4[(size_t)row * 4 + lane];
    float dv = g_dinv[row];

    float sh = 0.f, sa = 0.f;
    #pragma unroll
    for (int f = 0; f < 16; f++) {
        int src = f >> 2;
        float ch, ca;
        if ((f & 3) == 0)      { ch = hv.x; ca = acc.x; }
        else if ((f & 3) == 1) { ch = hv.y; ca = acc.y; }
        else if ((f & 3) == 2) { ch = hv.z; ca = acc.z; }
        else                   { ch = hv.w; ca = acc.w; }
        float hf = __shfl_sync(0xffffffffu, ch, src);
        float af = __shfl_sync(0xffffffffu, ca, src);
        sh = fmaf(hf, Wd[f * 32 + lane], sh);
        sa = fmaf(af, Wb[f * 32 + lane], sa);
    }
    float val = sh + dv * sa + __ldg(&b2[lane]);

    float m = val;
    #pragma unroll
    for (int d = 16; d; d >>= 1) m = fmaxf(m, __shfl_xor_sync(0xffffffffu, m, d));
    float ex = __expf(val - m);
    float sum = ex;
    #pragma unroll
    for (int d = 16; d; d >>= 1) sum += __shfl_xor_sync(0xffffffffu, sum, d);
    out[(size_t)row * 32 + lane] = val - m - __logf(sum);
}

// ---------------- launcher ----------------------------------------------------
extern "C" void kernel_launch(void* const* d_in, const int* in_sizes, int n_in,
                              void* d_out, int out_size) {
    const float* x   = (const float*)d_in[0];
    const void*  ei  = d_in[1];
    const float* ew  = (const float*)d_in[2];
    const float* W10 = (const float*)d_in[3];
    const float* W11 = (const float*)d_in[4];
    const float* b1  = (const float*)d_in[5];
    const float* W20 = (const float*)d_in[6];
    const float* W21 = (const float*)d_in[7];
    const float* b2  = (const float*)d_in[8];
    float* out = (float*)d_out;

    int N = in_sizes[0] / 128;
    int E = in_sizes[2];
    int NB = (N + 2047) / 2048;

    k_cnt<<<(E / 2 + 255) / 256, 256>>>(ei, E);
    k_scan_local<<<NB, 1024>>>(N, E, NB);
    k_scatter<<<(E + 255) / 256, 256>>>(ei, ew, E);
    k_gemm1<<<(N + 63) / 64, 256>>>(x, W10, W11, N, E);
    k_layer1<<<(N * 32 + 1023) / 1024, 1024>>>(b1, N);
    k_layer2<<<(N * 32 + 1023) / 1024, 1024>>>(W20, W21, b2, out, N);
}